// round 13
// baseline (speedup 1.0000x reference)
#include <cuda_runtime.h>
#include <math.h>

#define G    256
#define N0   1024
#define EE   4096
#define F    64
#define EDDI 4096
#define DH   128
#define NF   16
#define NT   512
#define QG   32

typedef unsigned long long u64;

// ---------------- device scratch (no allocations allowed) ----------------
__device__ float  g_bufA[G * N0 * F];   // H buffer, 64 MB
__device__ float  g_bufB[G * N0 * F];   // O buffer, 64 MB
__device__ float2 g_epk [G * EE];       // packed (src, coef) CSR payload, 8 MB
__device__ float4 g_eA  [G * EE];       // packed edge records (src,tgt,w), 16 MB
__device__ float4 g_eB  [G * EE];       // ping-pong partner, 16 MB
__device__ float  g_feat[G * DH];
__device__ float  g_Q   [G * NF * DH];
__device__ float  g_Bb  [G * DH];
__device__ float  g_accv[G * DH];
__device__ float  g_hh  [G * DH];
__device__ float  g_Hx  [G * DH];
__device__ float  g_Hy  [G * DH];
__device__ float  g_dummy[4];

// ---------------- dummy pre-kernels: keep ncu's profiled slot on k_graph ----------------
__global__ void k_pre1() { g_dummy[0] = 1.f; }
__global__ void k_pre2() { g_dummy[1] = 1.f; }
__global__ void k_pre3() { g_dummy[2] = 1.f; }

#define DEG_SCALE 524288.0f          // 2^19 fixed point for degree accumulation

// ---------------- per-graph GCN + SAGPool pipeline (1 CTA per graph) ----------------
__global__ __launch_bounds__(NT, 2) void k_graph(
    const float* __restrict__ x,
    const float* __restrict__ ew,
    const int*   __restrict__ ei,
    const float* __restrict__ W1, const float* __restrict__ b1,
    const float* __restrict__ sr1, const float* __restrict__ sn1, const float* __restrict__ sb1,
    const float* __restrict__ W2, const float* __restrict__ b2,
    const float* __restrict__ sr2, const float* __restrict__ sn2, const float* __restrict__ sb2,
    const float* __restrict__ W3, const float* __restrict__ b3,
    const float* __restrict__ sr3, const float* __restrict__ sn3, const float* __restrict__ sb3)
{
    const int g = blockIdx.x;
    const int tid = threadIdx.x;
    const int lane = tid & 31;
    const int wrp  = tid >> 5;            // 16 warps

    __shared__ __align__(16) float s_W[F * F];        // 16 KB
    __shared__ float s_score[N0];                     // 4 KB
    __shared__ float s_z[N0];                         // 4 KB (alias: perm ints)
    __shared__ float s_deg[N0];                       // 4 KB (alias: tanh cache)
    __shared__ u64   s_key[N0];                       // 8 KB (alias: deg/cnt accum, readout scratch)
    __shared__ int   s_cnt[N0];                       // 4 KB (alias: newid)
    __shared__ int   s_off[N0 + 1];                   // 4 KB
    __shared__ int   s_wsum[16];
    __shared__ int   s_ecnt;
    __shared__ float s_b[F], s_root[F], s_nbr[F];
    __shared__ float s_sb;
    __shared__ float s_feat[2 * F];

    float* H = g_bufA + (size_t)g * N0 * F;     // GEMM output
    float* O = g_bufB + (size_t)g * N0 * F;     // conv output
    float2* epk = g_epk  + (size_t)g * EE;
    float4* eA  = g_eA   + (size_t)g * EE;
    float4* eB  = g_eB   + (size_t)g * EE;

    for (int i = tid; i < 2 * F; i += NT) s_feat[i] = 0.f;

    const float* xin = x + (size_t)g * N0 * F;
    const int*   cs  = ei + (size_t)g * 2 * EE;
    const int*   ct  = cs + EE;
    const float* cw  = ew + (size_t)g * EE;
    const float4* ein = eA;
    int n = N0;
    int ne = EE;

    int* s_perm = (int*)s_z;

    for (int layer = 0; layer < 3; layer++) {
        const int k = n >> 1;
        const float* W  = layer == 0 ? W1  : (layer == 1 ? W2  : W3);
        const float* bb = layer == 0 ? b1  : (layer == 1 ? b2  : b3);
        const float* rr = layer == 0 ? sr1 : (layer == 1 ? sr2 : sr3);
        const float* nv = layer == 0 ? sn1 : (layer == 1 ? sn2 : sn3);
        const float* sb = layer == 0 ? sb1 : (layer == 1 ? sb2 : sb3);

        // phase 1: load weights + init packed deg/cnt accumulator
        for (int i = tid; i < F * F; i += NT) s_W[i] = W[i];
        if (tid < F) { s_b[tid] = bb[tid]; s_root[tid] = rr[tid]; s_nbr[tid] = nv[tid]; }
        if (tid == 0) s_sb = sb[0];
        for (int i = tid; i < n; i += NT) s_key[i] = ((u64)(unsigned)DEG_SCALE) << 32;
        __syncthreads();

        // phase 2: GEMM. layer 0 reads x linearly; later layers read O rows
        // through perm and fold tanh into the final accumulators (linearity).
        {
            int sub = tid & 15;
            int o0 = sub * 4;
            for (int nb = (tid >> 4) * 4; nb < n; nb += (NT / 16) * 4) {
                const float4 *x0, *x1, *x2, *x3;
                float sc0, sc1, sc2, sc3;
                if (layer == 0) {
                    x0 = (const float4*)(xin + (size_t)(nb + 0) * F);
                    x1 = (const float4*)(xin + (size_t)(nb + 1) * F);
                    x2 = (const float4*)(xin + (size_t)(nb + 2) * F);
                    x3 = (const float4*)(xin + (size_t)(nb + 3) * F);
                    sc0 = sc1 = sc2 = sc3 = 1.f;
                } else {
                    int r0 = s_perm[nb + 0], r1 = s_perm[nb + 1];
                    int r2 = s_perm[nb + 2], r3 = s_perm[nb + 3];
                    sc0 = s_deg[nb + 0]; sc1 = s_deg[nb + 1];
                    sc2 = s_deg[nb + 2]; sc3 = s_deg[nb + 3];
                    x0 = (const float4*)(O + (size_t)r0 * F);
                    x1 = (const float4*)(O + (size_t)r1 * F);
                    x2 = (const float4*)(O + (size_t)r2 * F);
                    x3 = (const float4*)(O + (size_t)r3 * F);
                }
                float acc[4][4];
                #pragma unroll
                for (int a = 0; a < 4; a++)
                    #pragma unroll
                    for (int c = 0; c < 4; c++) acc[a][c] = 0.f;
                #pragma unroll 2
                for (int i4 = 0; i4 < 16; i4++) {
                    float4 xa = __ldg(&x0[i4]);
                    float4 xb = __ldg(&x1[i4]);
                    float4 xc = __ldg(&x2[i4]);
                    float4 xd = __ldg(&x3[i4]);
                    #pragma unroll
                    for (int r = 0; r < 4; r++) {
                        float4 w = *(const float4*)&s_W[(4 * i4 + r) * F + o0];
                        float va = (r == 0) ? xa.x : (r == 1) ? xa.y : (r == 2) ? xa.z : xa.w;
                        float vb = (r == 0) ? xb.x : (r == 1) ? xb.y : (r == 2) ? xb.z : xb.w;
                        float vc = (r == 0) ? xc.x : (r == 1) ? xc.y : (r == 2) ? xc.z : xc.w;
                        float vd = (r == 0) ? xd.x : (r == 1) ? xd.y : (r == 2) ? xd.z : xd.w;
                        acc[0][0] += va * w.x; acc[0][1] += va * w.y; acc[0][2] += va * w.z; acc[0][3] += va * w.w;
                        acc[1][0] += vb * w.x; acc[1][1] += vb * w.y; acc[1][2] += vb * w.z; acc[1][3] += vb * w.w;
                        acc[2][0] += vc * w.x; acc[2][1] += vc * w.y; acc[2][2] += vc * w.z; acc[2][3] += vc * w.w;
                        acc[3][0] += vd * w.x; acc[3][1] += vd * w.y; acc[3][2] += vd * w.z; acc[3][3] += vd * w.w;
                    }
                }
                float scl[4] = {sc0, sc1, sc2, sc3};
                #pragma unroll
                for (int a = 0; a < 4; a++) {
                    float4 r4;
                    r4.x = acc[a][0] * scl[a]; r4.y = acc[a][1] * scl[a];
                    r4.z = acc[a][2] * scl[a]; r4.w = acc[a][3] * scl[a];
                    *(float4*)&H[(size_t)(nb + a) * F + o0] = r4;
                }
            }
        }
        __syncthreads();

        // phase 3: deg/cnt single u64 atomic per edge.
        // Layer 0 additionally packs (s,t,w) into eA so ALL later passes read 1 LDG.128.
        if (layer == 0) {
            for (int e = tid; e < ne; e += NT) {
                float w = cw[e];
                int s = cs[e], t = ct[e];
                eA[e] = make_float4(__int_as_float(s), __int_as_float(t), w, 0.f);
                if (w != 0.f) {
                    unsigned fx = (unsigned)__float2uint_rn(w * DEG_SCALE);
                    atomicAdd(&s_key[t], ((u64)fx << 32) | 1ull);
                }
            }
            ein = eA;
        } else {
            for (int e = tid; e < ne; e += NT) {
                float4 r = __ldg(&ein[e]);
                if (r.z != 0.f) {
                    unsigned fx = (unsigned)__float2uint_rn(r.z * DEG_SCALE);
                    atomicAdd(&s_key[__float_as_int(r.y)], ((u64)fx << 32) | 1ull);
                }
            }
        }
        __syncthreads();
        for (int i = tid; i < n; i += NT) {
            u64 v = s_key[i];
            s_deg[i] = rsqrtf((float)(unsigned)(v >> 32) * (1.0f / DEG_SCALE));
            s_cnt[i] = (int)(unsigned)v;
        }
        __syncthreads();

        // phase 4: exclusive prefix scan of s_cnt -> s_off
        {
            const int m = (n + NT - 1) / NT;   // 2 or 1
            int base = tid * m;
            int pref[2]; int local = 0;
            #pragma unroll
            for (int j = 0; j < 2; j++) {
                if (j < m) {
                    pref[j] = local;
                    int idx = base + j;
                    local += (idx < n) ? s_cnt[idx] : 0;
                }
            }
            int v = local;
            #pragma unroll
            for (int off = 1; off < 32; off <<= 1) {
                int t2 = __shfl_up_sync(0xffffffffu, v, off);
                if (lane >= off) v += t2;
            }
            if (lane == 31) s_wsum[wrp] = v;
            __syncthreads();
            if (wrp == 0) {
                int wv = (lane < 16) ? s_wsum[lane] : 0;
                #pragma unroll
                for (int off = 1; off < 16; off <<= 1) {
                    int t2 = __shfl_up_sync(0xffffffffu, wv, off);
                    if (lane >= off) wv += t2;
                }
                if (lane < 16) s_wsum[lane] = wv;
            }
            __syncthreads();
            int excl = v - local + (wrp ? s_wsum[wrp - 1] : 0);
            #pragma unroll
            for (int j = 0; j < 2; j++) {
                if (j < m) {
                    int idx = base + j;
                    if (idx < n) s_off[idx] = excl + pref[j];
                }
            }
            if (tid == NT - 1) s_off[n] = excl + local;
        }
        __syncthreads();
        for (int i = tid; i < n; i += NT) s_cnt[i] = s_off[i];  // cursors
        __syncthreads();

        // phase 5: CSR placement: packed (src, coef = dinv[s]*w*dinv[t])
        for (int e = tid; e < ne; e += NT) {
            float4 r = __ldg(&ein[e]);
            if (r.z == 0.f) continue;
            int s = __float_as_int(r.x), t = __float_as_int(r.y);
            int pos = atomicAdd(&s_cnt[t], 1);
            epk[pos] = make_float2(r.x, s_deg[s] * r.z * s_deg[t]);
        }
        __syncthreads();

        // phase 6: gather aggregation: warp per target; lane covers 2*lane, 2*lane+1.
        // Next target's CSR range + self row prefetched before current edge loop.
        {
            int t = wrp;
            int p0 = 0, p1 = 0;
            float2 hs = make_float2(0.f, 0.f);
            if (t < n) {
                p0 = s_off[t]; p1 = s_off[t + 1];
                hs = *(const float2*)&H[t * F + 2 * lane];
            }
            while (t < n) {
                int tn = t + 16;
                int q0 = 0, q1 = 0;
                float2 hsn = make_float2(0.f, 0.f);
                if (tn < n) {
                    q0 = s_off[tn]; q1 = s_off[tn + 1];
                    hsn = *(const float2*)&H[tn * F + 2 * lane];
                }
                float di = s_deg[t];
                float c0 = di * di;
                float acc0 = hs.x * c0;
                float acc1 = hs.y * c0;
                int p = p0;
                for (; p + 4 <= p1; p += 4) {
                    float2 e0 = __ldg(&epk[p]);
                    float2 e1 = __ldg(&epk[p + 1]);
                    float2 e2 = __ldg(&epk[p + 2]);
                    float2 e3 = __ldg(&epk[p + 3]);
                    float2 v0 = *(const float2*)&H[__float_as_int(e0.x) * F + 2 * lane];
                    float2 v1 = *(const float2*)&H[__float_as_int(e1.x) * F + 2 * lane];
                    float2 v2 = *(const float2*)&H[__float_as_int(e2.x) * F + 2 * lane];
                    float2 v3 = *(const float2*)&H[__float_as_int(e3.x) * F + 2 * lane];
                    acc0 += e0.y * v0.x; acc1 += e0.y * v0.y;
                    acc0 += e1.y * v1.x; acc1 += e1.y * v1.y;
                    acc0 += e2.y * v2.x; acc1 += e2.y * v2.y;
                    acc0 += e3.y * v3.x; acc1 += e3.y * v3.y;
                }
                if (p + 2 <= p1) {
                    float2 e0 = __ldg(&epk[p]);
                    float2 e1 = __ldg(&epk[p + 1]);
                    float2 v0 = *(const float2*)&H[__float_as_int(e0.x) * F + 2 * lane];
                    float2 v1 = *(const float2*)&H[__float_as_int(e1.x) * F + 2 * lane];
                    acc0 += e0.y * v0.x; acc1 += e0.y * v0.y;
                    acc0 += e1.y * v1.x; acc1 += e1.y * v1.y;
                    p += 2;
                }
                if (p < p1) {
                    float2 e0 = __ldg(&epk[p]);
                    float2 v0 = *(const float2*)&H[__float_as_int(e0.x) * F + 2 * lane];
                    acc0 += e0.y * v0.x; acc1 += e0.y * v0.y;
                }
                float v0r = fmaxf(acc0 + s_b[2 * lane], 0.f);
                float v1r = fmaxf(acc1 + s_b[2 * lane + 1], 0.f);
                float2 orow; orow.x = v0r; orow.y = v1r;
                *(float2*)&O[t * F + 2 * lane] = orow;
                float sc = v0r * s_root[2 * lane] + v1r * s_root[2 * lane + 1];
                float zz = v0r * s_nbr[2 * lane]  + v1r * s_nbr[2 * lane + 1];
                #pragma unroll
                for (int off = 16; off > 0; off >>= 1) {
                    sc += __shfl_xor_sync(0xffffffffu, sc, off);
                    zz += __shfl_xor_sync(0xffffffffu, zz, off);
                }
                if (lane == 0) {
                    s_score[t] = sc + s_sb;
                    s_z[t] = zz;
                }
                t = tn; p0 = q0; p1 = q1; hs = hsn;
            }
        }
        __syncthreads();

        // phase 7: score neighbor term: smem atomics (packed reads)
        for (int e = tid; e < ne; e += NT) {
            float4 r = __ldg(&ein[e]);
            if (r.z != 0.f)
                atomicAdd(&s_score[__float_as_int(r.y)], r.z * s_z[__float_as_int(r.x)]);
        }
        __syncthreads();

        // phase 8: pack sortable keys + init newid(-1) + reset edge counter
        int* s_newid = s_cnt;
        for (int i = tid; i < n; i += NT) {
            unsigned bits = __float_as_uint(s_score[i]);
            unsigned u = (bits & 0x80000000u) ? ~bits : (bits | 0x80000000u);
            s_key[i] = ((u64)u << 32) | (unsigned)(0xffffffffu - i);
            s_newid[i] = -1;
        }
        if (tid == 0) s_ecnt = 0;
        __syncthreads();

        // bitonic sort descending on u64 keys, register stages for j<=16
        const int nwin = n >> 5;
        for (int w = wrp; w < nwin; w += 16) {
            int i = w * 32 + lane;
            u64 key = s_key[i];
            #pragma unroll
            for (int k2 = 2; k2 <= 32; k2 <<= 1) {
                bool up = ((i & k2) == 0);
                for (int j = k2 >> 1; j > 0; j >>= 1) {
                    u64 p = __shfl_xor_sync(0xffffffffu, key, j);
                    bool lower = ((lane & j) == 0);
                    bool takemax = (up == lower);
                    if (takemax == (p > key)) key = p;
                }
            }
            s_key[i] = key;
        }
        __syncthreads();
        for (int k2 = 64; k2 <= n; k2 <<= 1) {
            for (int j = k2 >> 1; j >= 32; j >>= 1) {
                for (int i = tid; i < n; i += NT) {
                    int ixj = i ^ j;
                    if (ixj > i) {
                        bool up = ((i & k2) == 0);
                        u64 a = s_key[i], b = s_key[ixj];
                        if (up ? (a < b) : (a > b)) { s_key[i] = b; s_key[ixj] = a; }
                    }
                }
                __syncthreads();
            }
            for (int w = wrp; w < nwin; w += 16) {
                int i = w * 32 + lane;
                u64 key = s_key[i];
                bool up = ((i & k2) == 0);
                #pragma unroll
                for (int j = 16; j > 0; j >>= 1) {
                    u64 p = __shfl_xor_sync(0xffffffffu, key, j);
                    bool lower = ((lane & j) == 0);
                    bool takemax = (up == lower);
                    if (takemax == (p > key)) key = p;
                }
                s_key[i] = key;
            }
            __syncthreads();
        }

        // phase 9: decode perm + tanh + newid fill (fused)
        for (int j = tid; j < k; j += NT) {
            u64 key = s_key[j];
            unsigned uhi = (unsigned)(key >> 32);
            unsigned bits = (uhi & 0x80000000u) ? (uhi & 0x7fffffffu) : ~uhi;
            int pj = (int)(0xffffffffu - (unsigned)key);
            s_perm[j] = pj;
            s_deg[j] = tanhf(__uint_as_float(bits));
            s_newid[pj] = j;
        }
        __syncthreads();

        // phase 11: readout directly from O[perm]·tanh  (scratch in dead s_key)
        {
            float* redM = (float*)s_key;
            float* redS = (float*)s_key + NT;
            int f = tid & 63, part = tid >> 6;        // 8 parts
            int chunk = k >> 3;
            int j0 = part * chunk, j1 = j0 + chunk;
            float m = -INFINITY, sm = 0.f;
            for (int j = j0; j < j1; j++) {
                float v = O[s_perm[j] * F + f] * s_deg[j];
                m = fmaxf(m, v); sm += v;
            }
            redM[tid] = m; redS[tid] = sm;
            __syncthreads();
            if (tid < F) {
                float mm = -INFINITY, ss = 0.f;
                #pragma unroll
                for (int p = 0; p < 8; p++) {
                    mm = fmaxf(mm, redM[p * 64 + tid]);
                    ss += redS[p * 64 + tid];
                }
                s_feat[tid]     += mm;
                s_feat[F + tid] += ss / (float)k;
            }
        }

        // phase 12: edge remap + compaction into ping-pong partner buffer
        if (layer < 2) {
            float4* dst = (ein == eA) ? eB : eA;
            for (int e = tid; e < ne; e += NT) {
                float4 r = __ldg(&ein[e]);
                int ns = s_newid[__float_as_int(r.x)];
                int nt = s_newid[__float_as_int(r.y)];
                if (ns >= 0 && nt >= 0 && r.z != 0.f) {
                    int pos = atomicAdd(&s_ecnt, 1);
                    dst[pos] = make_float4(__int_as_float(ns), __int_as_float(nt), r.z, 0.f);
                }
            }
            __syncthreads();
            ne = s_ecnt;
            ein = dst;
        } else {
            __syncthreads();
        }
        n = k;
    }
    for (int i = tid; i < 2 * F; i += NT) g_feat[g * DH + i] = s_feat[i];
}

// ---------------- NNConv prep (smem-tiled): Q[g,f,o] (f<NF), Bb+accv-zero (f==NF) ----------------
__global__ __launch_bounds__(128) void k_Q(const float* __restrict__ Wnn,
                                           const float* __restrict__ bnn) {
    int f  = blockIdx.x;    // 0..16 ; f==NF -> Bb via bnn (+ accv zeroing)
    int gb = blockIdx.y;    // 0..7
    int o  = threadIdx.x;
    __shared__ float s_ft[QG * DH];
    __shared__ float s_wt[32 * DH];

    for (int idx = o; idx < QG * DH; idx += 128)
        s_ft[idx] = g_feat[gb * QG * DH + idx];

    const float* wp = (f < NF) ? (Wnn + (size_t)f * DH * DH) : bnn;
    float acc[QG];
    #pragma unroll
    for (int g2 = 0; g2 < QG; g2++) acc[g2] = 0.f;

    for (int c = 0; c < 4; c++) {
        __syncthreads();
        for (int idx = o; idx < 32 * DH; idx += 128)
            s_wt[idx] = __ldg(&wp[c * 32 * DH + idx]);
        __syncthreads();
        #pragma unroll 4
        for (int ii = 0; ii < 32; ii++) {
            float wv = s_wt[ii * DH + o];
            int ib = c * 32 + ii;
            #pragma unroll
            for (int g2 = 0; g2 < QG; g2++)
                acc[g2] += s_ft[g2 * DH + ib] * wv;
        }
    }
    if (f < NF) {
        #pragma unroll
        for (int g2 = 0; g2 < QG; g2++)
            g_Q[((gb * QG + g2) * NF + f) * DH + o] = acc[g2];
    } else {
        #pragma unroll
        for (int g2 = 0; g2 < QG; g2++) {
            g_Bb[(gb * QG + g2) * DH + o] = acc[g2];
            g_accv[(gb * QG + g2) * DH + o] = 0.f;
        }
    }
}

__global__ __launch_bounds__(128) void k_msg(const float* __restrict__ attr,
                                             const int* __restrict__ dei) {
    int e = blockIdx.x, o = threadIdx.x;
    __shared__ float sa[NF];
    __shared__ int ssrc, stgt;
    if (o < NF) sa[o] = attr[e * NF + o];
    if (o == 0) { ssrc = dei[e]; stgt = dei[EDDI + e]; }
    __syncthreads();
    int s = ssrc, t = stgt;
    float m = g_Bb[s * DH + o];
    const float* q = g_Q + (size_t)(s * NF) * DH + o;
    #pragma unroll
    for (int f = 0; f < NF; f++) m += sa[f] * q[f * DH];
    atomicAdd(&g_accv[t * DH + o], m);
}

// h/Hx/Hy, smem-tiled over 32 graphs per block: weight traffic 49 MB -> 1.5 MB
__global__ __launch_bounds__(128) void k_h(const float* __restrict__ Wroot,
                                           const float* __restrict__ bc4,
                                           const float* __restrict__ Wl1, const float* __restrict__ bl1,
                                           const float* __restrict__ Wl2, const float* __restrict__ bl2) {
    int gb = blockIdx.x;    // 0..7
    int o  = threadIdx.x;
    __shared__ float s_f[QG * DH];    // 16 KB: feat tile
    __shared__ float s_w[16 * DH];    // 8 KB: weight chunk
    __shared__ float s_h[QG * DH];    // 16 KB: h tile

    for (int idx = o; idx < QG * DH; idx += 128)
        s_f[idx] = g_feat[gb * QG * DH + idx];

    float acc[QG];
    float bc = bc4[o];
    #pragma unroll
    for (int g2 = 0; g2 < QG; g2++)
        acc[g2] = g_accv[(gb * QG + g2) * DH + o] + bc;

    for (int c = 0; c < 8; c++) {
        __syncthreads();
        for (int idx = o; idx < 16 * DH; idx += 128)
            s_w[idx] = __ldg(&Wroot[c * 16 * DH + idx]);
        __syncthreads();
        #pragma unroll 4
        for (int ii = 0; ii < 16; ii++) {
            float wv = s_w[ii * DH + o];
            int ib = c * 16 + ii;
            #pragma unroll
            for (int g2 = 0; g2 < QG; g2++)
                acc[g2] += s_f[g2 * DH + ib] * wv;
        }
    }
    #pragma unroll
    for (int g2 = 0; g2 < QG; g2++) {
        float hv = fmaxf(acc[g2], 0.f);
        s_h[g2 * DH + o] = hv;
        g_hh[(gb * QG + g2) * DH + o] = hv;
    }

    // Hx = h @ Wl1 + bl1
    float b1v = bl1[o];
    #pragma unroll
    for (int g2 = 0; g2 < QG; g2++) acc[g2] = b1v;
    for (int c = 0; c < 8; c++) {
        __syncthreads();
        for (int idx = o; idx < 16 * DH; idx += 128)
            s_w[idx] = __ldg(&Wl1[c * 16 * DH + idx]);
        __syncthreads();
        #pragma unroll 4
        for (int ii = 0; ii < 16; ii++) {
            float wv = s_w[ii * DH + o];
            int ib = c * 16 + ii;
            #pragma unroll
            for (int g2 = 0; g2 < QG; g2++)
                acc[g2] += s_h[g2 * DH + ib] * wv;
        }
    }
    #pragma unroll
    for (int g2 = 0; g2 < QG; g2++)
        g_Hx[(gb * QG + g2) * DH + o] = acc[g2];

    // Hy = h @ Wl2 + bl2
    float b2v = bl2[o];
    #pragma unroll
    for (int g2 = 0; g2 < QG; g2++) acc[g2] = b2v;
    for (int c = 0; c < 8; c++) {
        __syncthreads();
        for (int idx = o; idx < 16 * DH; idx += 128)
            s_w[idx] = __ldg(&Wl2[c * 16 * DH + idx]);
        __syncthreads();
        #pragma unroll 4
        for (int ii = 0; ii < 16; ii++) {
            float wv = s_w[ii * DH + o];
            int ib = c * 16 + ii;
            #pragma unroll
            for (int g2 = 0; g2 < QG; g2++)
                acc[g2] += s_h[g2 * DH + ib] * wv;
        }
    }
    #pragma unroll
    for (int g2 = 0; g2 < QG; g2++)
        g_Hy[(gb * QG + g2) * DH + o] = acc[g2];
}

// warp-per-edge: float4 loads, scalar pos_x stores (out+1 base is only 4B aligned)
__global__ __launch_bounds__(256) void k_edge(const int* __restrict__ dei,
                                              const int* __restrict__ nei,
                                              float* __restrict__ out) {
    int warp = threadIdx.x >> 5, lane = threadIdx.x & 31;
    int e = blockIdx.x * 8 + warp;
    int neg = blockIdx.y;
    const int* ei = neg ? nei : dei;
    int s = ei[e], t = ei[EDDI + e];
    float4 a = ((const float4*)(g_Hx + (size_t)s * DH))[lane];
    float4 b = ((const float4*)(g_Hy + (size_t)t * DH))[lane];
    if (!neg) {
        float* po = out + 1 + 2 * EDDI + (size_t)e * DH + 4 * lane;
        po[0] = a.x; po[1] = a.y; po[2] = a.z; po[3] = a.w;
    }
    float p = a.x * b.x + a.y * b.y + a.z * b.z + a.w * b.w;
    #pragma unroll
    for (int off = 16; off > 0; off >>= 1) p += __shfl_xor_sync(0xffffffffu, p, off);
    if (lane == 0) out[1 + neg * EDDI + e] = p;
}

__global__ __launch_bounds__(256) void k_loss(float* __restrict__ out) {
    int tid = threadIdx.x;
    __shared__ float sred[256];
    float acc = 0.f;
    for (int i = tid; i < EDDI; i += 256) {
        float np = out[1 + i];
        float nn = out[1 + EDDI + i];
        acc += fmaxf(-np, 0.f) + log1pf(expf(-fabsf(np)));   // softplus(-np)
        acc += fmaxf(nn, 0.f) + log1pf(expf(-fabsf(nn)));    // softplus(nn)
    }
    sred[tid] = acc;
    __syncthreads();
    for (int s = 128; s > 0; s >>= 1) {
        if (tid < s) sred[tid] += sred[tid + s];
        __syncthreads();
    }
    if (tid == 0) out[0] = sred[0] / (float)EDDI;
}

// ---------------- launch ----------------
extern "C" void kernel_launch(void* const* d_in, const int* in_sizes, int n_in,
                              void* d_out, int out_size) {
    const float* x     = (const float*)d_in[0];
    const float* ew    = (const float*)d_in[1];
    const float* dattr = (const float*)d_in[2];
    const float* W1  = (const float*)d_in[4];  const float* b1  = (const float*)d_in[5];
    const float* sr1 = (const float*)d_in[6];  const float* sn1 = (const float*)d_in[7];  const float* sb1 = (const float*)d_in[8];
    const float* W2  = (const float*)d_in[9];  const float* b2  = (const float*)d_in[10];
    const float* sr2 = (const float*)d_in[11]; const float* sn2 = (const float*)d_in[12]; const float* sb2 = (const float*)d_in[13];
    const float* W3  = (const float*)d_in[14]; const float* b3  = (const float*)d_in[15];
    const float* sr3 = (const float*)d_in[16]; const float* sn3 = (const float*)d_in[17]; const float* sb3 = (const float*)d_in[18];
    const float* Wnn = (const float*)d_in[19]; const float* bnn = (const float*)d_in[20];
    const float* Wroot = (const float*)d_in[21]; const float* bc4 = (const float*)d_in[22];
    const float* Wl1 = (const float*)d_in[23]; const float* bl1 = (const float*)d_in[24];
    const float* Wl2 = (const float*)d_in[25]; const float* bl2 = (const float*)d_in[26];
    const int* ei  = (const int*)d_in[27];
    const int* dei = (const int*)d_in[28];
    const int* nei = (const int*)d_in[29];
    float* out = (float*)d_out;

    k_pre1<<<1, 1>>>();
    k_pre2<<<1, 1>>>();
    k_pre3<<<1, 1>>>();
    k_graph<<<G, NT>>>(x, ew, ei,
                       W1, b1, sr1, sn1, sb1,
                       W2, b2, sr2, sn2, sb2,
                       W3, b3, sr3, sn3, sb3);
    k_Q<<<dim3(NF + 1, 8), 128>>>(Wnn, bnn);
    k_msg<<<EDDI, 128>>>(dattr, dei);
    k_h<<<8, 128>>>(Wroot, bc4, Wl1, bl1, Wl2, bl2);
    k_edge<<<dim3(EDDI / 8, 2), 256>>>(dei, nei, out);
    k_loss<<<1, 256>>>(out);
}

// round 14
// speedup vs baseline: 1.0817x; 1.0817x over previous
#include <cuda_runtime.h>
#include <math.h>

#define G    256
#define N0   1024
#define EE   4096
#define F    64
#define EDDI 4096
#define DH   128
#define NF   16
#define NT   512
#define QG   32

typedef unsigned long long u64;

// ---------------- device scratch (no allocations allowed) ----------------
__device__ float  g_bufA[G * N0 * F];   // H buffer, 64 MB
__device__ float  g_bufB[G * N0 * F];   // O buffer, 64 MB
__device__ float2 g_epk [G * EE];       // packed (src, coef) CSR payload, 8 MB
__device__ float4 g_eA  [G * EE];       // packed edge records (src,tgt,w), 16 MB
__device__ float4 g_eB  [G * EE];       // ping-pong partner, 16 MB
__device__ float  g_feat[G * DH];
__device__ float  g_Q   [G * NF * DH];
__device__ float  g_Bb  [G * DH];
__device__ float  g_accv[G * DH];
__device__ float  g_hh  [G * DH];
__device__ float  g_Hx  [G * DH];
__device__ float  g_Hy  [G * DH];
__device__ float  g_dummy[4];

// ---------------- dummy pre-kernels: keep ncu's profiled slot on k_graph ----------------
__global__ void k_pre1() { g_dummy[0] = 1.f; }
__global__ void k_pre2() { g_dummy[1] = 1.f; }
__global__ void k_pre3() { g_dummy[2] = 1.f; }

#define DEG_SCALE 524288.0f          // 2^19 fixed point for degree accumulation

// ---------------- per-graph GCN + SAGPool pipeline (1 CTA per graph) ----------------
__global__ __launch_bounds__(NT, 2) void k_graph(
    const float* __restrict__ x,
    const float* __restrict__ ew,
    const int*   __restrict__ ei,
    const float* __restrict__ W1, const float* __restrict__ b1,
    const float* __restrict__ sr1, const float* __restrict__ sn1, const float* __restrict__ sb1,
    const float* __restrict__ W2, const float* __restrict__ b2,
    const float* __restrict__ sr2, const float* __restrict__ sn2, const float* __restrict__ sb2,
    const float* __restrict__ W3, const float* __restrict__ b3,
    const float* __restrict__ sr3, const float* __restrict__ sn3, const float* __restrict__ sb3)
{
    const int g = blockIdx.x;
    const int tid = threadIdx.x;
    const int lane = tid & 31;
    const int wrp  = tid >> 5;            // 16 warps

    __shared__ __align__(16) float s_W[F * F];        // 16 KB
    __shared__ float s_score[N0];                     // 4 KB
    __shared__ float s_z[N0];                         // 4 KB (alias: perm ints)
    __shared__ float s_deg[N0];                       // 4 KB (alias: tanh cache)
    __shared__ u64   s_key[N0];                       // 8 KB (alias: deg/cnt accum, readout scratch)
    __shared__ int   s_cnt[N0];                       // 4 KB (alias: newid)
    __shared__ int   s_off[N0 + 1];                   // 4 KB
    __shared__ int   s_wsum[16];
    __shared__ int   s_ecnt;
    __shared__ float s_b[F], s_root[F], s_nbr[F];
    __shared__ float s_sb;
    __shared__ float s_feat[2 * F];

    float* H = g_bufA + (size_t)g * N0 * F;     // GEMM output
    float* O = g_bufB + (size_t)g * N0 * F;     // conv output
    float2* epk = g_epk  + (size_t)g * EE;
    float4* eA  = g_eA   + (size_t)g * EE;
    float4* eB  = g_eB   + (size_t)g * EE;

    for (int i = tid; i < 2 * F; i += NT) s_feat[i] = 0.f;

    const float* xin = x + (size_t)g * N0 * F;
    const int*   cs  = ei + (size_t)g * 2 * EE;
    const int*   ct  = cs + EE;
    const float* cw  = ew + (size_t)g * EE;
    const float4* ein = eA;
    int n = N0;
    int ne = EE;

    int* s_perm = (int*)s_z;

    for (int layer = 0; layer < 3; layer++) {
        const int k = n >> 1;
        const float* W  = layer == 0 ? W1  : (layer == 1 ? W2  : W3);
        const float* bb = layer == 0 ? b1  : (layer == 1 ? b2  : b3);
        const float* rr = layer == 0 ? sr1 : (layer == 1 ? sr2 : sr3);
        const float* nv = layer == 0 ? sn1 : (layer == 1 ? sn2 : sn3);
        const float* sb = layer == 0 ? sb1 : (layer == 1 ? sb2 : sb3);

        // phase 1: load weights + init packed deg/cnt accumulator
        for (int i = tid; i < F * F; i += NT) s_W[i] = W[i];
        if (tid < F) { s_b[tid] = bb[tid]; s_root[tid] = rr[tid]; s_nbr[tid] = nv[tid]; }
        if (tid == 0) s_sb = sb[0];
        for (int i = tid; i < n; i += NT) s_key[i] = ((u64)(unsigned)DEG_SCALE) << 32;
        __syncthreads();

        // phase 2: GEMM. layer 0 reads x linearly; later layers read O rows
        // through perm and fold tanh into the final accumulators (linearity).
        {
            int sub = tid & 15;
            int o0 = sub * 4;
            for (int nb = (tid >> 4) * 4; nb < n; nb += (NT / 16) * 4) {
                const float4 *x0, *x1, *x2, *x3;
                float sc0, sc1, sc2, sc3;
                if (layer == 0) {
                    x0 = (const float4*)(xin + (size_t)(nb + 0) * F);
                    x1 = (const float4*)(xin + (size_t)(nb + 1) * F);
                    x2 = (const float4*)(xin + (size_t)(nb + 2) * F);
                    x3 = (const float4*)(xin + (size_t)(nb + 3) * F);
                    sc0 = sc1 = sc2 = sc3 = 1.f;
                } else {
                    int r0 = s_perm[nb + 0], r1 = s_perm[nb + 1];
                    int r2 = s_perm[nb + 2], r3 = s_perm[nb + 3];
                    sc0 = s_deg[nb + 0]; sc1 = s_deg[nb + 1];
                    sc2 = s_deg[nb + 2]; sc3 = s_deg[nb + 3];
                    x0 = (const float4*)(O + (size_t)r0 * F);
                    x1 = (const float4*)(O + (size_t)r1 * F);
                    x2 = (const float4*)(O + (size_t)r2 * F);
                    x3 = (const float4*)(O + (size_t)r3 * F);
                }
                float acc[4][4];
                #pragma unroll
                for (int a = 0; a < 4; a++)
                    #pragma unroll
                    for (int c = 0; c < 4; c++) acc[a][c] = 0.f;
                #pragma unroll 2
                for (int i4 = 0; i4 < 16; i4++) {
                    float4 xa = __ldg(&x0[i4]);
                    float4 xb = __ldg(&x1[i4]);
                    float4 xc = __ldg(&x2[i4]);
                    float4 xd = __ldg(&x3[i4]);
                    #pragma unroll
                    for (int r = 0; r < 4; r++) {
                        float4 w = *(const float4*)&s_W[(4 * i4 + r) * F + o0];
                        float va = (r == 0) ? xa.x : (r == 1) ? xa.y : (r == 2) ? xa.z : xa.w;
                        float vb = (r == 0) ? xb.x : (r == 1) ? xb.y : (r == 2) ? xb.z : xb.w;
                        float vc = (r == 0) ? xc.x : (r == 1) ? xc.y : (r == 2) ? xc.z : xc.w;
                        float vd = (r == 0) ? xd.x : (r == 1) ? xd.y : (r == 2) ? xd.z : xd.w;
                        acc[0][0] += va * w.x; acc[0][1] += va * w.y; acc[0][2] += va * w.z; acc[0][3] += va * w.w;
                        acc[1][0] += vb * w.x; acc[1][1] += vb * w.y; acc[1][2] += vb * w.z; acc[1][3] += vb * w.w;
                        acc[2][0] += vc * w.x; acc[2][1] += vc * w.y; acc[2][2] += vc * w.z; acc[2][3] += vc * w.w;
                        acc[3][0] += vd * w.x; acc[3][1] += vd * w.y; acc[3][2] += vd * w.z; acc[3][3] += vd * w.w;
                    }
                }
                float scl[4] = {sc0, sc1, sc2, sc3};
                #pragma unroll
                for (int a = 0; a < 4; a++) {
                    float4 r4;
                    r4.x = acc[a][0] * scl[a]; r4.y = acc[a][1] * scl[a];
                    r4.z = acc[a][2] * scl[a]; r4.w = acc[a][3] * scl[a];
                    *(float4*)&H[(size_t)(nb + a) * F + o0] = r4;
                }
            }
        }
        __syncthreads();

        // phase 3: deg/cnt single u64 atomic per edge.
        // Layer 0 additionally packs (s,t,w) into eA so ALL later passes read 1 LDG.128.
        if (layer == 0) {
            for (int e = tid; e < ne; e += NT) {
                float w = cw[e];
                int s = cs[e], t = ct[e];
                eA[e] = make_float4(__int_as_float(s), __int_as_float(t), w, 0.f);
                if (w != 0.f) {
                    unsigned fx = (unsigned)__float2uint_rn(w * DEG_SCALE);
                    atomicAdd(&s_key[t], ((u64)fx << 32) | 1ull);
                }
            }
            ein = eA;
        } else {
            for (int e = tid; e < ne; e += NT) {
                float4 r = __ldg(&ein[e]);
                if (r.z != 0.f) {
                    unsigned fx = (unsigned)__float2uint_rn(r.z * DEG_SCALE);
                    atomicAdd(&s_key[__float_as_int(r.y)], ((u64)fx << 32) | 1ull);
                }
            }
        }
        __syncthreads();
        for (int i = tid; i < n; i += NT) {
            u64 v = s_key[i];
            s_deg[i] = rsqrtf((float)(unsigned)(v >> 32) * (1.0f / DEG_SCALE));
            s_cnt[i] = (int)(unsigned)v;
        }
        __syncthreads();

        // phase 4: exclusive prefix scan of s_cnt -> s_off
        {
            const int m = (n + NT - 1) / NT;   // 2 or 1
            int base = tid * m;
            int pref[2]; int local = 0;
            #pragma unroll
            for (int j = 0; j < 2; j++) {
                if (j < m) {
                    pref[j] = local;
                    int idx = base + j;
                    local += (idx < n) ? s_cnt[idx] : 0;
                }
            }
            int v = local;
            #pragma unroll
            for (int off = 1; off < 32; off <<= 1) {
                int t2 = __shfl_up_sync(0xffffffffu, v, off);
                if (lane >= off) v += t2;
            }
            if (lane == 31) s_wsum[wrp] = v;
            __syncthreads();
            if (wrp == 0) {
                int wv = (lane < 16) ? s_wsum[lane] : 0;
                #pragma unroll
                for (int off = 1; off < 16; off <<= 1) {
                    int t2 = __shfl_up_sync(0xffffffffu, wv, off);
                    if (lane >= off) wv += t2;
                }
                if (lane < 16) s_wsum[lane] = wv;
            }
            __syncthreads();
            int excl = v - local + (wrp ? s_wsum[wrp - 1] : 0);
            #pragma unroll
            for (int j = 0; j < 2; j++) {
                if (j < m) {
                    int idx = base + j;
                    if (idx < n) s_off[idx] = excl + pref[j];
                }
            }
            if (tid == NT - 1) s_off[n] = excl + local;
        }
        __syncthreads();
        for (int i = tid; i < n; i += NT) s_cnt[i] = s_off[i];  // cursors
        __syncthreads();

        // phase 5: CSR placement: packed (src, coef = dinv[s]*w*dinv[t])
        for (int e = tid; e < ne; e += NT) {
            float4 r = __ldg(&ein[e]);
            if (r.z == 0.f) continue;
            int s = __float_as_int(r.x), t = __float_as_int(r.y);
            int pos = atomicAdd(&s_cnt[t], 1);
            epk[pos] = make_float2(r.x, s_deg[s] * r.z * s_deg[t]);
        }
        __syncthreads();

        // phase 6: gather aggregation: warp per target; lane covers 2*lane, 2*lane+1.
        // Next target's CSR range + self row prefetched before current edge loop.
        {
            int t = wrp;
            int p0 = 0, p1 = 0;
            float2 hs = make_float2(0.f, 0.f);
            if (t < n) {
                p0 = s_off[t]; p1 = s_off[t + 1];
                hs = *(const float2*)&H[t * F + 2 * lane];
            }
            while (t < n) {
                int tn = t + 16;
                int q0 = 0, q1 = 0;
                float2 hsn = make_float2(0.f, 0.f);
                if (tn < n) {
                    q0 = s_off[tn]; q1 = s_off[tn + 1];
                    hsn = *(const float2*)&H[tn * F + 2 * lane];
                }
                float di = s_deg[t];
                float c0 = di * di;
                float acc0 = hs.x * c0;
                float acc1 = hs.y * c0;
                int p = p0;
                for (; p + 4 <= p1; p += 4) {
                    float2 e0 = __ldg(&epk[p]);
                    float2 e1 = __ldg(&epk[p + 1]);
                    float2 e2 = __ldg(&epk[p + 2]);
                    float2 e3 = __ldg(&epk[p + 3]);
                    float2 v0 = *(const float2*)&H[__float_as_int(e0.x) * F + 2 * lane];
                    float2 v1 = *(const float2*)&H[__float_as_int(e1.x) * F + 2 * lane];
                    float2 v2 = *(const float2*)&H[__float_as_int(e2.x) * F + 2 * lane];
                    float2 v3 = *(const float2*)&H[__float_as_int(e3.x) * F + 2 * lane];
                    acc0 += e0.y * v0.x; acc1 += e0.y * v0.y;
                    acc0 += e1.y * v1.x; acc1 += e1.y * v1.y;
                    acc0 += e2.y * v2.x; acc1 += e2.y * v2.y;
                    acc0 += e3.y * v3.x; acc1 += e3.y * v3.y;
                }
                if (p + 2 <= p1) {
                    float2 e0 = __ldg(&epk[p]);
                    float2 e1 = __ldg(&epk[p + 1]);
                    float2 v0 = *(const float2*)&H[__float_as_int(e0.x) * F + 2 * lane];
                    float2 v1 = *(const float2*)&H[__float_as_int(e1.x) * F + 2 * lane];
                    acc0 += e0.y * v0.x; acc1 += e0.y * v0.y;
                    acc0 += e1.y * v1.x; acc1 += e1.y * v1.y;
                    p += 2;
                }
                if (p < p1) {
                    float2 e0 = __ldg(&epk[p]);
                    float2 v0 = *(const float2*)&H[__float_as_int(e0.x) * F + 2 * lane];
                    acc0 += e0.y * v0.x; acc1 += e0.y * v0.y;
                }
                float v0r = fmaxf(acc0 + s_b[2 * lane], 0.f);
                float v1r = fmaxf(acc1 + s_b[2 * lane + 1], 0.f);
                float2 orow; orow.x = v0r; orow.y = v1r;
                *(float2*)&O[t * F + 2 * lane] = orow;
                float sc = v0r * s_root[2 * lane] + v1r * s_root[2 * lane + 1];
                float zz = v0r * s_nbr[2 * lane]  + v1r * s_nbr[2 * lane + 1];
                #pragma unroll
                for (int off = 16; off > 0; off >>= 1) {
                    sc += __shfl_xor_sync(0xffffffffu, sc, off);
                    zz += __shfl_xor_sync(0xffffffffu, zz, off);
                }
                if (lane == 0) {
                    s_score[t] = sc + s_sb;
                    s_z[t] = zz;
                }
                t = tn; p0 = q0; p1 = q1; hs = hsn;
            }
        }
        __syncthreads();

        // phase 7: score neighbor term: smem atomics (packed reads)
        for (int e = tid; e < ne; e += NT) {
            float4 r = __ldg(&ein[e]);
            if (r.z != 0.f)
                atomicAdd(&s_score[__float_as_int(r.y)], r.z * s_z[__float_as_int(r.x)]);
        }
        __syncthreads();

        // phase 8: pack sortable keys + init newid(-1) + reset edge counter
        int* s_newid = s_cnt;
        for (int i = tid; i < n; i += NT) {
            unsigned bits = __float_as_uint(s_score[i]);
            unsigned u = (bits & 0x80000000u) ? ~bits : (bits | 0x80000000u);
            s_key[i] = ((u64)u << 32) | (unsigned)(0xffffffffu - i);
            s_newid[i] = -1;
        }
        if (tid == 0) s_ecnt = 0;
        __syncthreads();

        // bitonic sort descending on u64 keys, register stages for j<=16
        const int nwin = n >> 5;
        for (int w = wrp; w < nwin; w += 16) {
            int i = w * 32 + lane;
            u64 key = s_key[i];
            #pragma unroll
            for (int k2 = 2; k2 <= 32; k2 <<= 1) {
                bool up = ((i & k2) == 0);
                for (int j = k2 >> 1; j > 0; j >>= 1) {
                    u64 p = __shfl_xor_sync(0xffffffffu, key, j);
                    bool lower = ((lane & j) == 0);
                    bool takemax = (up == lower);
                    if (takemax == (p > key)) key = p;
                }
            }
            s_key[i] = key;
        }
        __syncthreads();
        for (int k2 = 64; k2 <= n; k2 <<= 1) {
            for (int j = k2 >> 1; j >= 32; j >>= 1) {
                for (int i = tid; i < n; i += NT) {
                    int ixj = i ^ j;
                    if (ixj > i) {
                        bool up = ((i & k2) == 0);
                        u64 a = s_key[i], b = s_key[ixj];
                        if (up ? (a < b) : (a > b)) { s_key[i] = b; s_key[ixj] = a; }
                    }
                }
                __syncthreads();
            }
            for (int w = wrp; w < nwin; w += 16) {
                int i = w * 32 + lane;
                u64 key = s_key[i];
                bool up = ((i & k2) == 0);
                #pragma unroll
                for (int j = 16; j > 0; j >>= 1) {
                    u64 p = __shfl_xor_sync(0xffffffffu, key, j);
                    bool lower = ((lane & j) == 0);
                    bool takemax = (up == lower);
                    if (takemax == (p > key)) key = p;
                }
                s_key[i] = key;
            }
            __syncthreads();
        }

        // phase 9: decode perm + tanh + newid fill (fused)
        for (int j = tid; j < k; j += NT) {
            u64 key = s_key[j];
            unsigned uhi = (unsigned)(key >> 32);
            unsigned bits = (uhi & 0x80000000u) ? (uhi & 0x7fffffffu) : ~uhi;
            int pj = (int)(0xffffffffu - (unsigned)key);
            s_perm[j] = pj;
            s_deg[j] = tanhf(__uint_as_float(bits));
            s_newid[pj] = j;
        }
        __syncthreads();

        // phase 11: readout directly from O[perm]·tanh  (scratch in dead s_key)
        {
            float* redM = (float*)s_key;
            float* redS = (float*)s_key + NT;
            int f = tid & 63, part = tid >> 6;        // 8 parts
            int chunk = k >> 3;
            int j0 = part * chunk, j1 = j0 + chunk;
            float m = -INFINITY, sm = 0.f;
            for (int j = j0; j < j1; j++) {
                float v = O[s_perm[j] * F + f] * s_deg[j];
                m = fmaxf(m, v); sm += v;
            }
            redM[tid] = m; redS[tid] = sm;
            __syncthreads();
            if (tid < F) {
                float mm = -INFINITY, ss = 0.f;
                #pragma unroll
                for (int p = 0; p < 8; p++) {
                    mm = fmaxf(mm, redM[p * 64 + tid]);
                    ss += redS[p * 64 + tid];
                }
                s_feat[tid]     += mm;
                s_feat[F + tid] += ss / (float)k;
            }
        }

        // phase 12: edge remap + compaction into ping-pong partner buffer
        if (layer < 2) {
            float4* dst = (ein == eA) ? eB : eA;
            for (int e = tid; e < ne; e += NT) {
                float4 r = __ldg(&ein[e]);
                int ns = s_newid[__float_as_int(r.x)];
                int nt = s_newid[__float_as_int(r.y)];
                if (ns >= 0 && nt >= 0 && r.z != 0.f) {
                    int pos = atomicAdd(&s_ecnt, 1);
                    dst[pos] = make_float4(__int_as_float(ns), __int_as_float(nt), r.z, 0.f);
                }
            }
            __syncthreads();
            ne = s_ecnt;
            ein = dst;
        } else {
            __syncthreads();
        }
        n = k;
    }
    for (int i = tid; i < 2 * F; i += NT) g_feat[g * DH + i] = s_feat[i];
}

// ---------------- NNConv prep (smem-tiled): Q[g,f,o] (f<NF), Bb+accv-zero (f==NF) ----------------
__global__ __launch_bounds__(128) void k_Q(const float* __restrict__ Wnn,
                                           const float* __restrict__ bnn) {
    int f  = blockIdx.x;    // 0..16 ; f==NF -> Bb via bnn (+ accv zeroing)
    int gb = blockIdx.y;    // 0..7
    int o  = threadIdx.x;
    __shared__ float s_ft[QG * DH];
    __shared__ float s_wt[32 * DH];

    for (int idx = o; idx < QG * DH; idx += 128)
        s_ft[idx] = g_feat[gb * QG * DH + idx];

    const float* wp = (f < NF) ? (Wnn + (size_t)f * DH * DH) : bnn;
    float acc[QG];
    #pragma unroll
    for (int g2 = 0; g2 < QG; g2++) acc[g2] = 0.f;

    for (int c = 0; c < 4; c++) {
        __syncthreads();
        for (int idx = o; idx < 32 * DH; idx += 128)
            s_wt[idx] = __ldg(&wp[c * 32 * DH + idx]);
        __syncthreads();
        #pragma unroll 4
        for (int ii = 0; ii < 32; ii++) {
            float wv = s_wt[ii * DH + o];
            int ib = c * 32 + ii;
            #pragma unroll
            for (int g2 = 0; g2 < QG; g2++)
                acc[g2] += s_ft[g2 * DH + ib] * wv;
        }
    }
    if (f < NF) {
        #pragma unroll
        for (int g2 = 0; g2 < QG; g2++)
            g_Q[((gb * QG + g2) * NF + f) * DH + o] = acc[g2];
    } else {
        #pragma unroll
        for (int g2 = 0; g2 < QG; g2++) {
            g_Bb[(gb * QG + g2) * DH + o] = acc[g2];
            g_accv[(gb * QG + g2) * DH + o] = 0.f;
        }
    }
}

__global__ __launch_bounds__(128) void k_msg(const float* __restrict__ attr,
                                             const int* __restrict__ dei) {
    int e = blockIdx.x, o = threadIdx.x;
    __shared__ float sa[NF];
    __shared__ int ssrc, stgt;
    if (o < NF) sa[o] = attr[e * NF + o];
    if (o == 0) { ssrc = dei[e]; stgt = dei[EDDI + e]; }
    __syncthreads();
    int s = ssrc, t = stgt;
    float m = g_Bb[s * DH + o];
    const float* q = g_Q + (size_t)(s * NF) * DH + o;
    #pragma unroll
    for (int f = 0; f < NF; f++) m += sa[f] * q[f * DH];
    atomicAdd(&g_accv[t * DH + o], m);
}

// h = relu(acc + feat@Wroot + bc4) ; then Hx = h@Wl1+bl1, Hy = h@Wl2+bl2 (fused, 1 block/graph)
__global__ __launch_bounds__(128) void k_h(const float* __restrict__ Wroot,
                                           const float* __restrict__ bc4,
                                           const float* __restrict__ Wl1, const float* __restrict__ bl1,
                                           const float* __restrict__ Wl2, const float* __restrict__ bl2) {
    int g = blockIdx.x, o = threadIdx.x;
    __shared__ float sh[DH];
    const float* fe = g_feat + g * DH;
    float acc = g_accv[g * DH + o] + bc4[o];
    #pragma unroll 8
    for (int i = 0; i < DH; i++) acc += fe[i] * Wroot[i * DH + o];
    float hv = fmaxf(acc, 0.f);
    g_hh[g * DH + o] = hv;
    sh[o] = hv;
    __syncthreads();
    float a = bl1[o], b = bl2[o];
    #pragma unroll 8
    for (int i = 0; i < DH; i++) {
        float h2 = sh[i];
        a += h2 * Wl1[i * DH + o];
        b += h2 * Wl2[i * DH + o];
    }
    g_Hx[g * DH + o] = a;
    g_Hy[g * DH + o] = b;
}

// warp-per-edge: float4 loads, scalar pos_x stores (out+1 base is only 4B aligned)
__global__ __launch_bounds__(256) void k_edge(const int* __restrict__ dei,
                                              const int* __restrict__ nei,
                                              float* __restrict__ out) {
    int warp = threadIdx.x >> 5, lane = threadIdx.x & 31;
    int e = blockIdx.x * 8 + warp;
    int neg = blockIdx.y;
    const int* ei = neg ? nei : dei;
    int s = ei[e], t = ei[EDDI + e];
    float4 a = ((const float4*)(g_Hx + (size_t)s * DH))[lane];
    float4 b = ((const float4*)(g_Hy + (size_t)t * DH))[lane];
    if (!neg) {
        float* po = out + 1 + 2 * EDDI + (size_t)e * DH + 4 * lane;
        po[0] = a.x; po[1] = a.y; po[2] = a.z; po[3] = a.w;
    }
    float p = a.x * b.x + a.y * b.y + a.z * b.z + a.w * b.w;
    #pragma unroll
    for (int off = 16; off > 0; off >>= 1) p += __shfl_xor_sync(0xffffffffu, p, off);
    if (lane == 0) out[1 + neg * EDDI + e] = p;
}

__global__ __launch_bounds__(256) void k_loss(float* __restrict__ out) {
    int tid = threadIdx.x;
    __shared__ float sred[256];
    float acc = 0.f;
    for (int i = tid; i < EDDI; i += 256) {
        float np = out[1 + i];
        float nn = out[1 + EDDI + i];
        acc += fmaxf(-np, 0.f) + log1pf(expf(-fabsf(np)));   // softplus(-np)
        acc += fmaxf(nn, 0.f) + log1pf(expf(-fabsf(nn)));    // softplus(nn)
    }
    sred[tid] = acc;
    __syncthreads();
    for (int s = 128; s > 0; s >>= 1) {
        if (tid < s) sred[tid] += sred[tid + s];
        __syncthreads();
    }
    if (tid == 0) out[0] = sred[0] / (float)EDDI;
}

// ---------------- launch ----------------
extern "C" void kernel_launch(void* const* d_in, const int* in_sizes, int n_in,
                              void* d_out, int out_size) {
    const float* x     = (const float*)d_in[0];
    const float* ew    = (const float*)d_in[1];
    const float* dattr = (const float*)d_in[2];
    const float* W1  = (const float*)d_in[4];  const float* b1  = (const float*)d_in[5];
    const float* sr1 = (const float*)d_in[6];  const float* sn1 = (const float*)d_in[7];  const float* sb1 = (const float*)d_in[8];
    const float* W2  = (const float*)d_in[9];  const float* b2  = (const float*)d_in[10];
    const float* sr2 = (const float*)d_in[11]; const float* sn2 = (const float*)d_in[12]; const float* sb2 = (const float*)d_in[13];
    const float* W3  = (const float*)d_in[14]; const float* b3  = (const float*)d_in[15];
    const float* sr3 = (const float*)d_in[16]; const float* sn3 = (const float*)d_in[17]; const float* sb3 = (const float*)d_in[18];
    const float* Wnn = (const float*)d_in[19]; const float* bnn = (const float*)d_in[20];
    const float* Wroot = (const float*)d_in[21]; const float* bc4 = (const float*)d_in[22];
    const float* Wl1 = (const float*)d_in[23]; const float* bl1 = (const float*)d_in[24];
    const float* Wl2 = (const float*)d_in[25]; const float* bl2 = (const float*)d_in[26];
    const int* ei  = (const int*)d_in[27];
    const int* dei = (const int*)d_in[28];
    const int* nei = (const int*)d_in[29];
    float* out = (float*)d_out;

    k_pre1<<<1, 1>>>();
    k_pre2<<<1, 1>>>();
    k_pre3<<<1, 1>>>();
    k_graph<<<G, NT>>>(x, ew, ei,
                       W1, b1, sr1, sn1, sb1,
                       W2, b2, sr2, sn2, sb2,
                       W3, b3, sr3, sn3, sb3);
    k_Q<<<dim3(NF + 1, 8), 128>>>(Wnn, bnn);
    k_msg<<<EDDI, 128>>>(dattr, dei);
    k_h<<<G, 128>>>(Wroot, bc4, Wl1, bl1, Wl2, bl2);
    k_edge<<<dim3(EDDI / 8, 2), 256>>>(dei, nei, out);
    k_loss<<<1, 256>>>(out);
}